// round 15
// baseline (speedup 1.0000x reference)
#include <cuda_runtime.h>
#include <cuda_fp16.h>
#include <cstdint>

#define GN 9216      // H*W
#define GC 256       // C
#define GO 320       // 2*CQ + C
#define NT 72        // GN / 128
#define LOG2E 1.4426950408889634f
#define SOFF  20.0f  // fixed softmax offset (log2 domain)

// f16 staging written by QKV GEMM
__device__ __half g_q2[2][GN][64];   // q*log2e: [n][0:32]=hi, [n][32:64]=lo
__device__ __half g_k2[2][GN][64];   // k:       [n][0:32]=hi, [n][32:64]=lo
__device__ __half g_vh[2][GC][GN];   // v: [c][n]

// ---------------- smem layout (bytes) ----------------
#define QK_PITCH 144    // 128B data + 16 pad (conflict-free ldmatrix)
#define V_PITCH  272    // 256B data + 16 pad
#define SK_OFF   0
#define SQ_OFF0  18432
#define SQ_OFF1  36864
#define SV_OFF0  55296
#define SV_OFF1  127104
#define SMEM_TOTAL 198912   // 194.25 KB

// ---------------- helpers ----------------
__device__ __forceinline__ uint32_t smem_u32(const void* p) {
    uint32_t a;
    asm("{ .reg .u64 t; cvta.to.shared.u64 t, %1; cvt.u32.u64 %0, t; }"
        : "=r"(a) : "l"(p));
    return a;
}
__device__ __forceinline__ void cp16(uint32_t dst, const void* src) {
    asm volatile("cp.async.cg.shared.global [%0], [%1], 16;" :: "r"(dst), "l"(src));
}
#define CP_COMMIT() asm volatile("cp.async.commit_group;" ::: "memory")
#define CP_WAIT1()  asm volatile("cp.async.wait_group 1;" ::: "memory")

__device__ __forceinline__ unsigned long long pk2(float lo, float hi) {
    unsigned long long r;
    asm("mov.b64 %0, {%1, %2};" : "=l"(r) : "f"(lo), "f"(hi));
    return r;
}
__device__ __forceinline__ void upk2(unsigned long long v, float &lo, float &hi) {
    asm("mov.b64 {%0, %1}, %2;" : "=f"(lo), "=f"(hi) : "l"(v));
}
__device__ __forceinline__ unsigned long long ffma2(unsigned long long a,
                                                    unsigned long long b,
                                                    unsigned long long c) {
    unsigned long long d;
    asm("fma.rn.f32x2 %0, %1, %2, %3;" : "=l"(d) : "l"(a), "l"(b), "l"(c));
    return d;
}

#define LDM_X2(r0, r1, a) \
    asm volatile("ldmatrix.sync.aligned.m8n8.x2.shared.b16 {%0,%1}, [%2];" \
                 : "=r"(r0), "=r"(r1) : "r"(a))
#define LDM_X4(r0, r1, r2, r3, a) \
    asm volatile("ldmatrix.sync.aligned.m8n8.x4.shared.b16 {%0,%1,%2,%3}, [%4];" \
                 : "=r"(r0), "=r"(r1), "=r"(r2), "=r"(r3) : "r"(a))
#define MMA16816(d, a, b0v, b1v) \
    asm volatile("mma.sync.aligned.m16n8k16.row.col.f32.f16.f16.f32 " \
                 "{%0,%1,%2,%3}, {%4,%5,%6,%7}, {%8,%9}, {%0,%1,%2,%3};" \
                 : "+f"((d)[0]), "+f"((d)[1]), "+f"((d)[2]), "+f"((d)[3]) \
                 : "r"((a)[0]), "r"((a)[1]), "r"((a)[2]), "r"((a)[3]), \
                   "r"(b0v), "r"(b1v))

// exp2 on fp32 inputs (full precision), pack result pair to f16x2 {lo=t0, hi=t1}
__device__ __forceinline__ uint32_t exp_pair(float t0, float t1) {
    float e0, e1;
    asm("ex2.approx.f32 %0, %1;" : "=f"(e0) : "f"(t0));
    asm("ex2.approx.f32 %0, %1;" : "=f"(e1) : "f"(t1));
    uint32_t r;
    asm("cvt.rn.satfinite.f16x2.f32 %0, %1, %2;" : "=r"(r) : "f"(e1), "f"(e0));
    return r;
}

// ---------------- Kernel 1: qkv = w @ x -> f16 hi/lo staging ----------------
// 64(m) x 256(n) tile, 8x8 per thread, f32x2 accumulation
__global__ __launch_bounds__(256) void qkv_gemm(const float* __restrict__ x,
                                                const float* __restrict__ w) {
    __shared__ float ws[16][72];    // [k][m]  (64 + pad)
    __shared__ float xs[16][260];   // [k][n]  (256 + pad)
    const int t = threadIdx.x;
    const int b = blockIdx.z;
    const int m0 = blockIdx.y * 64;
    const int n0 = blockIdx.x * 256;
    const int tn = t & 31, tm = t >> 5;
    const float* xb = x + (size_t)b * GC * GN;

    unsigned long long acc2[8][4];
#pragma unroll
    for (int i2 = 0; i2 < 8; i2++)
#pragma unroll
        for (int p = 0; p < 4; p++) acc2[i2][p] = 0ULL;

    for (int k0 = 0; k0 < GC; k0 += 16) {
        // ws: 64 m x 16 k
#pragma unroll
        for (int r = 0; r < 4; r++) {
            int i = t + r * 256;
            ws[i & 15][i >> 4] = w[(m0 + (i >> 4)) * GC + k0 + (i & 15)];
        }
        // xs: 16 k x 256 n (float4)
#pragma unroll
        for (int r = 0; r < 4; r++) {
            int i = t + r * 256;               // 0..1023
            int kk = i >> 6, nn4 = (i & 63) * 4;
            float4 v = *reinterpret_cast<const float4*>(
                &xb[(size_t)(k0 + kk) * GN + n0 + nn4]);
            *reinterpret_cast<float4*>(&xs[kk][nn4]) = v;
        }
        __syncthreads();
#pragma unroll
        for (int kk = 0; kk < 16; kk++) {
            float4 a0 = *reinterpret_cast<const float4*>(&ws[kk][tm * 8]);
            float4 a1 = *reinterpret_cast<const float4*>(&ws[kk][tm * 8 + 4]);
            float4 b0 = *reinterpret_cast<const float4*>(&xs[kk][tn * 8]);
            float4 b1 = *reinterpret_cast<const float4*>(&xs[kk][tn * 8 + 4]);
            unsigned long long bp[4] = {pk2(b0.x, b0.y), pk2(b0.z, b0.w),
                                        pk2(b1.x, b1.y), pk2(b1.z, b1.w)};
            float av[8] = {a0.x, a0.y, a0.z, a0.w, a1.x, a1.y, a1.z, a1.w};
#pragma unroll
            for (int i2 = 0; i2 < 8; i2++) {
                unsigned long long aa = pk2(av[i2], av[i2]);
#pragma unroll
                for (int p = 0; p < 4; p++)
                    acc2[i2][p] = ffma2(aa, bp[p], acc2[i2][p]);
            }
        }
        __syncthreads();
    }
#pragma unroll
    for (int i2 = 0; i2 < 8; i2++) {
        int o = m0 + tm * 8 + i2;
        float vals[8];
#pragma unroll
        for (int p = 0; p < 4; p++) upk2(acc2[i2][p], vals[2 * p], vals[2 * p + 1]);
#pragma unroll
        for (int j2 = 0; j2 < 8; j2++) {
            int n = n0 + tn * 8 + j2;
            float a = vals[j2];
            if (o < 32) {
                float a2 = a * LOG2E;
                __half hi = __float2half_rn(a2);
                g_q2[b][n][o]      = hi;
                g_q2[b][n][o + 32] = __float2half_rn(a2 - __half2float(hi));
            } else if (o < 64) {
                __half hi = __float2half_rn(a);
                g_k2[b][n][o - 32] = hi;
                g_k2[b][n][o]      = __float2half_rn(a - __half2float(hi));
            } else {
                g_vh[b][o - 64][n] = __float2half_rn(a);
            }
        }
    }
}

// ---------------- tile loaders (cp.async, 512 threads) ----------------
__device__ __forceinline__ void load_qk_tile(uint32_t sdst, const __half* base,
                                             int n0, int t) {
    const char* g = (const char*)(base + (size_t)n0 * 64);
#pragma unroll
    for (int k = 0; k < 2; k++) {
        int gi = t + k * 512;                 // 0..1023
        int row = gi >> 3, c8 = gi & 7;
        cp16(sdst + row * QK_PITCH + c8 * 16, g + gi * 16);
    }
}
__device__ __forceinline__ void load_v_tile(uint32_t sdst, const __half* base,
                                            int i0, int t) {
#pragma unroll
    for (int k = 0; k < 8; k++) {
        int gi = t + k * 512;                 // 0..4095
        int row = gi >> 4, c16 = gi & 15;
        const char* src = (const char*)(base + (size_t)row * GN + i0) + c16 * 16;
        cp16(sdst + row * V_PITCH + c16 * 16, src);
    }
}

// ---------------- Kernel 2: mma.sync flash attention, 512 thr, c-split ----------------
__global__ __launch_bounds__(512, 1) void attn_kernel(const float* __restrict__ x,
                                                      const float* __restrict__ gamma_p,
                                                      float* __restrict__ out) {
    extern __shared__ char sm[];
    const uint32_t sb = smem_u32(sm);
    const int t = threadIdx.x;
    const int w = t >> 5, lane = t & 31;
    const int wq = w & 7;        // j-row group (16 rows)
    const int wg = w >> 3;       // c-half: 0 -> c 0..127, 1 -> c 128..255
    const int b = blockIdx.y;
    const int j0 = blockIdx.x * 128;

    const __half* qb_g = &g_q2[b][0][0];
    const __half* kb_g = &g_k2[b][0][0];
    const __half* vb_g = &g_vh[b][0][0];

    // V rows 256..263: row 256 = ones (gives l via MMA), 257..263 = zeros
    for (int idx = t; idx < 2048; idx += 512) {
        int buf = idx >> 10;
        int rr = (idx >> 7) & 7;
        int col = idx & 127;
        *(__half*)(sm + (buf ? SV_OFF1 : SV_OFF0) + (256 + rr) * V_PITCH + col * 2)
            = __float2half(rr == 0 ? 1.0f : 0.0f);
    }

    // prologue: G0 = {K, Q0, V0}, G1 = {Q1, V1}
    load_qk_tile(sb + SK_OFF, kb_g, j0, t);
    load_qk_tile(sb + SQ_OFF0, qb_g, 0, t);
    load_v_tile(sb + SV_OFF0, vb_g, 0, t);
    CP_COMMIT();
    load_qk_tile(sb + SQ_OFF1, qb_g, 128, t);
    load_v_tile(sb + SV_OFF1, vb_g, 128, t);
    CP_COMMIT();
    CP_WAIT1();                 // G0 landed
    __syncthreads();

    // K hi A-fragments, resident all kernel: rows j = wq*16..wq*16+15
    uint32_t kh[2][4];
    {
        uint32_t kaddr = sb + SK_OFF + (wq * 16 + (lane & 15)) * QK_PITCH
                       + ((lane >> 4) & 1) * 16;
        LDM_X4(kh[0][0], kh[0][1], kh[0][2], kh[0][3], kaddr);
        LDM_X4(kh[1][0], kh[1][1], kh[1][2], kh[1][3], kaddr + 32);
    }

    // x4 B-operand offsets: lanes 0-15 -> tile n8=even, lanes 16-31 -> n8=odd
    const uint32_t qoff4 = (lane & 7) * QK_PITCH + ((lane >> 3) & 1) * 16
                         + (lane >> 4) * (8 * QK_PITCH);
    const uint32_t voff4 = (lane & 7) * V_PITCH + ((lane >> 3) & 1) * 16
                         + (lane >> 4) * (8 * V_PITCH) + wg * (128 * V_PITCH);
    const uint32_t voff2 = (lane & 7) * V_PITCH + ((lane >> 3) & 1) * 16
                         + 256 * V_PITCH;                      // ones row
    const uint32_t qbuf[2] = {sb + SQ_OFF0 + qoff4, sb + SQ_OFF1 + qoff4};
    const uint32_t vbuf4[2] = {sb + SV_OFF0 + voff4, sb + SV_OFF1 + voff4};
    const uint32_t vbuf2[2] = {sb + SV_OFF0 + voff2, sb + SV_OFF1 + voff2};

    float acc[17][4];
#pragma unroll
    for (int nc = 0; nc < 17; nc++)
#pragma unroll
        for (int q = 0; q < 4; q++) acc[nc][q] = 0.f;

#pragma unroll 1
    for (int tt = 0; tt < NT; tt++) {
        if (tt) { CP_WAIT1(); __syncthreads(); }
        const uint32_t qa  = qbuf[tt & 1];
        const uint32_t va4 = vbuf4[tt & 1];
        const uint32_t va2 = vbuf2[tt & 1];

#pragma unroll
        for (int ks8 = 0; ks8 < 8; ks8++) {       // 16-wide i chunk
            float sc0[4] = {-SOFF, -SOFF, -SOFF, -SOFF};
            float sc1[4] = {-SOFF, -SOFF, -SOFF, -SOFF};
#pragma unroll
            for (int ks = 0; ks < 2; ks++) {
                uint32_t h0, h1, h2, h3, l0, l1, l2, l3;
                LDM_X4(h0, h1, h2, h3, qa + (2 * ks8) * 8 * QK_PITCH + ks * 32);
                LDM_X4(l0, l1, l2, l3, qa + (2 * ks8) * 8 * QK_PITCH + 64 + ks * 32);
                MMA16816(sc0, kh[ks], h0, h1);   // kh·qh (tile 0)
                MMA16816(sc0, kh[ks], l0, l1);   // kh·ql (tile 0)
                MMA16816(sc1, kh[ks], h2, h3);   // kh·qh (tile 1)
                MMA16816(sc1, kh[ks], l2, l3);   // kh·ql (tile 1)
            }
            // exp2 (fp32 MUFU) -> P A-fragment
            uint32_t pa[4];
            pa[0] = exp_pair(sc0[0], sc0[1]);
            pa[1] = exp_pair(sc0[2], sc0[3]);
            pa[2] = exp_pair(sc1[0], sc1[1]);
            pa[3] = exp_pair(sc1[2], sc1[3]);
            // PV over this warp's c-half: 8 x4 loads = 16 n8 chunks, + ones row
            const uint32_t vrow4 = va4 + ks8 * 32;
#pragma unroll
            for (int nc2 = 0; nc2 < 8; nc2++) {
                uint32_t b0, b1, b2, b3;
                LDM_X4(b0, b1, b2, b3, vrow4 + nc2 * (16 * V_PITCH));
                MMA16816(acc[2 * nc2],     pa, b0, b1);
                MMA16816(acc[2 * nc2 + 1], pa, b2, b3);
            }
            {
                uint32_t b0, b1;
                LDM_X2(b0, b1, va2 + ks8 * 32);
                MMA16816(acc[16], pa, b0, b1);
            }
        }

        __syncthreads();
        if (tt + 2 < NT) {
            load_qk_tile(sb + (tt & 1 ? SQ_OFF1 : SQ_OFF0), qb_g, (tt + 2) * 128, t);
            load_v_tile(sb + (tt & 1 ? SV_OFF1 : SV_OFF0), vb_g, (tt + 2) * 128, t);
        }
        CP_COMMIT();
    }

    // ---------------- epilogue ----------------
    // l[j] from the ones-column: acc[16][0] rows r, acc[16][2] rows r+8,
    // valid at lanes with (lane&3)==0. Broadcast across each quad.
    float l0 = __shfl_sync(0xffffffffu, acc[16][0], lane & 0x1C);
    float l1 = __shfl_sync(0xffffffffu, acc[16][2], lane & 0x1C);
    const float g = gamma_p[0];
    const float gl0 = g / l0;
    const float gl1 = g / l1;

    const int jA = j0 + wq * 16 + (lane >> 2);
    const int cb = (lane & 3) * 2;
#pragma unroll
    for (int nc = 0; nc < 16; nc++) {
        int c = wg * 128 + nc * 8 + cb;
        size_t o00 = ((size_t)(b * GC + c)) * GN + jA;   // (c,   jA)
        size_t o10 = o00 + GN;                            // (c+1, jA)
        out[o00]     = gl0 * acc[nc][0] + x[o00];
        out[o10]     = gl0 * acc[nc][1] + x[o10];
        out[o00 + 8] = gl1 * acc[nc][2] + x[o00 + 8];    // (c,   jA+8)
        out[o10 + 8] = gl1 * acc[nc][3] + x[o10 + 8];    // (c+1, jA+8)
    }
}

extern "C" void kernel_launch(void* const* d_in, const int* in_sizes, int n_in,
                              void* d_out, int out_size) {
    const float* x     = (const float*)d_in[0];
    const float* w     = (const float*)d_in[1];
    const float* gamma = (const float*)d_in[2];
    float* out = (float*)d_out;

    cudaFuncSetAttribute(attn_kernel,
                         cudaFuncAttributeMaxDynamicSharedMemorySize, SMEM_TOTAL);

    dim3 g1(GN / 256, GO / 64, 2);     // (36, 5, 2)
    qkv_gemm<<<g1, 256>>>(x, w);

    dim3 g2(NT, 2);                    // (72, 2) = 144 CTAs ~ 1 wave
    attn_kernel<<<g2, 512, SMEM_TOTAL>>>(x, gamma, out);
}

// round 16
// speedup vs baseline: 1.2809x; 1.2809x over previous
#include <cuda_runtime.h>
#include <cuda_fp16.h>
#include <cstdint>

#define GN 9216      // H*W
#define GC 256       // C
#define GO 320       // 2*CQ + C
#define NT 72        // GN / 128
#define LOG2E 1.4426950408889634f
#define SOFF  20.0f  // fixed softmax offset (log2 domain)

// f16 staging written by QKV GEMM
__device__ __half g_q2[2][GN][64];   // q*log2e: [n][0:32]=hi (lo unused)
__device__ __half g_k2[2][GN][64];   // k:       [n][0:32]=hi (lo unused)
__device__ __half g_vh[2][GC][GN];   // v: [c][n]

// ---------------- smem layout (bytes) ----------------
#define QK_PITCH 80     // 64B data + 16 pad (conflict-free ldmatrix)
#define V_PITCH  272    // 256B data + 16 pad
#define SK_OFF   0
#define SQ_OFF0  10240
#define SQ_OFF1  20480
#define SV_OFF0  30720
#define SV_OFF1  102528
#define SMEM_TOTAL 174336   // 170.25 KB

// ---------------- helpers ----------------
__device__ __forceinline__ uint32_t smem_u32(const void* p) {
    uint32_t a;
    asm("{ .reg .u64 t; cvta.to.shared.u64 t, %1; cvt.u32.u64 %0, t; }"
        : "=r"(a) : "l"(p));
    return a;
}
__device__ __forceinline__ void cp16(uint32_t dst, const void* src) {
    asm volatile("cp.async.cg.shared.global [%0], [%1], 16;" :: "r"(dst), "l"(src));
}
#define CP_COMMIT() asm volatile("cp.async.commit_group;" ::: "memory")
#define CP_WAIT1()  asm volatile("cp.async.wait_group 1;" ::: "memory")

__device__ __forceinline__ unsigned long long pk2(float lo, float hi) {
    unsigned long long r;
    asm("mov.b64 %0, {%1, %2};" : "=l"(r) : "f"(lo), "f"(hi));
    return r;
}
__device__ __forceinline__ void upk2(unsigned long long v, float &lo, float &hi) {
    asm("mov.b64 {%0, %1}, %2;" : "=f"(lo), "=f"(hi) : "l"(v));
}
__device__ __forceinline__ unsigned long long ffma2(unsigned long long a,
                                                    unsigned long long b,
                                                    unsigned long long c) {
    unsigned long long d;
    asm("fma.rn.f32x2 %0, %1, %2, %3;" : "=l"(d) : "l"(a), "l"(b), "l"(c));
    return d;
}

#define LDM_X2(r0, r1, a) \
    asm volatile("ldmatrix.sync.aligned.m8n8.x2.shared.b16 {%0,%1}, [%2];" \
                 : "=r"(r0), "=r"(r1) : "r"(a))
#define LDM_X4(r0, r1, r2, r3, a) \
    asm volatile("ldmatrix.sync.aligned.m8n8.x4.shared.b16 {%0,%1,%2,%3}, [%4];" \
                 : "=r"(r0), "=r"(r1), "=r"(r2), "=r"(r3) : "r"(a))
#define MMA16816(d, a, b0v, b1v) \
    asm volatile("mma.sync.aligned.m16n8k16.row.col.f32.f16.f16.f32 " \
                 "{%0,%1,%2,%3}, {%4,%5,%6,%7}, {%8,%9}, {%0,%1,%2,%3};" \
                 : "+f"((d)[0]), "+f"((d)[1]), "+f"((d)[2]), "+f"((d)[3]) \
                 : "r"((a)[0]), "r"((a)[1]), "r"((a)[2]), "r"((a)[3]), \
                   "r"(b0v), "r"(b1v))

// exp2 on fp32 inputs (full precision), pack result pair to f16x2 {lo=t0, hi=t1}
__device__ __forceinline__ uint32_t exp_pair(float t0, float t1) {
    float e0, e1;
    asm("ex2.approx.f32 %0, %1;" : "=f"(e0) : "f"(t0));
    asm("ex2.approx.f32 %0, %1;" : "=f"(e1) : "f"(t1));
    uint32_t r;
    asm("cvt.rn.satfinite.f16x2.f32 %0, %1, %2;" : "=r"(r) : "f"(e1), "f"(e0));
    return r;
}

// ---------------- Kernel 1: qkv = w @ x -> f16 staging (4x4, f32x2) ----------------
__global__ __launch_bounds__(256) void qkv_gemm(const float* __restrict__ x,
                                                const float* __restrict__ w) {
    __shared__ float ws[16][68];
    __shared__ float xs[16][68];
    const int t = threadIdx.x;
    const int b = blockIdx.z;
    const int m0 = blockIdx.y * 64;
    const int n0 = blockIdx.x * 64;
    const int tn = t & 15, tm = t >> 4;
    const float* xb = x + (size_t)b * GC * GN;
    unsigned long long acc2[4][2];
#pragma unroll
    for (int i2 = 0; i2 < 4; i2++) { acc2[i2][0] = 0ULL; acc2[i2][1] = 0ULL; }

    for (int k0 = 0; k0 < GC; k0 += 16) {
#pragma unroll
        for (int r = 0; r < 4; r++) {
            int i = t + r * 256;
            ws[i & 15][i >> 4] = w[(m0 + (i >> 4)) * GC + k0 + (i & 15)];
        }
#pragma unroll
        for (int r = 0; r < 4; r++) {
            int i = t + r * 256;
            xs[i >> 6][i & 63] = xb[(size_t)(k0 + (i >> 6)) * GN + n0 + (i & 63)];
        }
        __syncthreads();
#pragma unroll
        for (int kk = 0; kk < 16; kk++) {
            float4 a  = *reinterpret_cast<const float4*>(&ws[kk][tm * 4]);
            float4 bb = *reinterpret_cast<const float4*>(&xs[kk][tn * 4]);
            unsigned long long b01 = pk2(bb.x, bb.y);
            unsigned long long b23 = pk2(bb.z, bb.w);
            float av[4] = {a.x, a.y, a.z, a.w};
#pragma unroll
            for (int i2 = 0; i2 < 4; i2++) {
                unsigned long long aa = pk2(av[i2], av[i2]);
                acc2[i2][0] = ffma2(aa, b01, acc2[i2][0]);
                acc2[i2][1] = ffma2(aa, b23, acc2[i2][1]);
            }
        }
        __syncthreads();
    }
#pragma unroll
    for (int i2 = 0; i2 < 4; i2++) {
        int o = m0 + tm * 4 + i2;
        float vals[4];
        upk2(acc2[i2][0], vals[0], vals[1]);
        upk2(acc2[i2][1], vals[2], vals[3]);
#pragma unroll
        for (int j2 = 0; j2 < 4; j2++) {
            int n = n0 + tn * 4 + j2;
            float a = vals[j2];
            if (o < 32)       g_q2[b][n][o]      = __float2half_rn(a * LOG2E);
            else if (o < 64)  g_k2[b][n][o - 32] = __float2half_rn(a);
            else              g_vh[b][o - 64][n] = __float2half_rn(a);
        }
    }
}

// ---------------- tile loaders (cp.async) ----------------
// Q/K tile: 128 rows x 32 halfs hi (64B used) from 128B global rows
__device__ __forceinline__ void load_qk_tile(uint32_t sdst, const __half* base,
                                             int n0, int t) {
    const char* g = (const char*)(base + (size_t)n0 * 64);
#pragma unroll
    for (int k = 0; k < 2; k++) {
        int gi = t + k * 256;                 // 0..511
        int row = gi >> 2, c4 = gi & 3;
        cp16(sdst + row * QK_PITCH + c4 * 16, g + row * 128 + c4 * 16);
    }
}
__device__ __forceinline__ void load_v_tile(uint32_t sdst, const __half* base,
                                            int i0, int t) {
#pragma unroll
    for (int k = 0; k < 16; k++) {
        int gi = t + k * 256;                 // 0..4095
        int row = gi >> 4, c16 = gi & 15;
        const char* src = (const char*)(base + (size_t)row * GN + i0) + c16 * 16;
        cp16(sdst + row * V_PITCH + c16 * 16, src);
    }
}

// ---------------- Kernel 2: mma.sync flash attention ----------------
__global__ __launch_bounds__(256, 1) void attn_kernel(const float* __restrict__ x,
                                                      const float* __restrict__ gamma_p,
                                                      float* __restrict__ out) {
    extern __shared__ char sm[];
    const uint32_t sb = smem_u32(sm);
    const int t = threadIdx.x;
    const int w = t >> 5, lane = t & 31;
    const int b = blockIdx.y;
    const int j0 = blockIdx.x * 128;

    const __half* qb_g = &g_q2[b][0][0];
    const __half* kb_g = &g_k2[b][0][0];
    const __half* vb_g = &g_vh[b][0][0];

    // V rows 256..263: row 256 = ones (gives l via MMA), 257..263 = zeros
    for (int idx = t; idx < 2048; idx += 256) {
        int buf = idx >> 10;
        int rr = (idx >> 7) & 7;
        int col = idx & 127;
        *(__half*)(sm + (buf ? SV_OFF1 : SV_OFF0) + (256 + rr) * V_PITCH + col * 2)
            = __float2half(rr == 0 ? 1.0f : 0.0f);
    }

    // prologue: G0 = {K, Q0, V0}, G1 = {Q1, V1}
    load_qk_tile(sb + SK_OFF, kb_g, j0, t);
    load_qk_tile(sb + SQ_OFF0, qb_g, 0, t);
    load_v_tile(sb + SV_OFF0, vb_g, 0, t);
    CP_COMMIT();
    load_qk_tile(sb + SQ_OFF1, qb_g, 128, t);
    load_v_tile(sb + SV_OFF1, vb_g, 128, t);
    CP_COMMIT();
    CP_WAIT1();                 // G0 landed
    __syncthreads();

    // K A-fragments, resident all kernel: rows j = w*16..w*16+15
    uint32_t kh[2][4];
    {
        uint32_t kaddr = sb + SK_OFF + (w * 16 + (lane & 15)) * QK_PITCH
                       + ((lane >> 4) & 1) * 16;
        LDM_X4(kh[0][0], kh[0][1], kh[0][2], kh[0][3], kaddr);
        LDM_X4(kh[1][0], kh[1][1], kh[1][2], kh[1][3], kaddr + 32);
    }

    // x4 B-operand offsets: lanes 0-15 -> tile n8=even, lanes 16-31 -> n8=odd
    const uint32_t qoff4 = (lane & 7) * QK_PITCH + ((lane >> 3) & 1) * 16
                         + (lane >> 4) * (8 * QK_PITCH);
    const uint32_t voff4 = (lane & 7) * V_PITCH + ((lane >> 3) & 1) * 16
                         + (lane >> 4) * (8 * V_PITCH);
    const uint32_t voff2 = (lane & 7) * V_PITCH + ((lane >> 3) & 1) * 16
                         + 256 * V_PITCH;                      // ones row
    const uint32_t qbuf[2] = {sb + SQ_OFF0 + qoff4, sb + SQ_OFF1 + qoff4};
    const uint32_t vbuf4[2] = {sb + SV_OFF0 + voff4, sb + SV_OFF1 + voff4};
    const uint32_t vbuf2[2] = {sb + SV_OFF0 + voff2, sb + SV_OFF1 + voff2};

    float acc[33][4];
#pragma unroll
    for (int nc = 0; nc < 33; nc++)
#pragma unroll
        for (int q = 0; q < 4; q++) acc[nc][q] = 0.f;

#pragma unroll 1
    for (int tt = 0; tt < NT; tt++) {
        if (tt) { CP_WAIT1(); __syncthreads(); }
        const uint32_t qa  = qbuf[tt & 1];
        const uint32_t va4 = vbuf4[tt & 1];
        const uint32_t va2 = vbuf2[tt & 1];

#pragma unroll
        for (int ks8 = 0; ks8 < 8; ks8++) {       // 16-wide i chunk
            float sc0[4] = {-SOFF, -SOFF, -SOFF, -SOFF};
            float sc1[4] = {-SOFF, -SOFF, -SOFF, -SOFF};
#pragma unroll
            for (int ks = 0; ks < 2; ks++) {
                uint32_t h0, h1, h2, h3;
                // both n8 tiles' f16 Q in one x4
                LDM_X4(h0, h1, h2, h3, qa + (2 * ks8) * 8 * QK_PITCH + ks * 32);
                MMA16816(sc0, kh[ks], h0, h1);   // tile 0
                MMA16816(sc1, kh[ks], h2, h3);   // tile 1
            }
            // exp2 (fp32 MUFU) -> P A-fragment
            uint32_t pa[4];
            pa[0] = exp_pair(sc0[0], sc0[1]);
            pa[1] = exp_pair(sc0[2], sc0[3]);
            pa[2] = exp_pair(sc1[0], sc1[1]);
            pa[3] = exp_pair(sc1[2], sc1[3]);
            // PV: D[j][c] += P * V^T  (16 x4 loads = 32 n8 chunks, + ones row)
            const uint32_t vrow4 = va4 + ks8 * 32;
#pragma unroll
            for (int nc2 = 0; nc2 < 16; nc2++) {
                uint32_t b0, b1, b2, b3;
                LDM_X4(b0, b1, b2, b3, vrow4 + nc2 * (16 * V_PITCH));
                MMA16816(acc[2 * nc2],     pa, b0, b1);
                MMA16816(acc[2 * nc2 + 1], pa, b2, b3);
            }
            {
                uint32_t b0, b1;
                LDM_X2(b0, b1, va2 + ks8 * 32);
                MMA16816(acc[32], pa, b0, b1);
            }
        }

        __syncthreads();
        if (tt + 2 < NT) {
            load_qk_tile(sb + (tt & 1 ? SQ_OFF1 : SQ_OFF0), qb_g, (tt + 2) * 128, t);
            load_v_tile(sb + (tt & 1 ? SV_OFF1 : SV_OFF0), vb_g, (tt + 2) * 128, t);
        }
        CP_COMMIT();
    }

    // ---------------- epilogue ----------------
    // l[j] from the ones-column (c=256): acc[32][0] rows r, acc[32][2] rows r+8,
    // valid at lanes with (lane&3)==0. Broadcast across each quad.
    float l0 = __shfl_sync(0xffffffffu, acc[32][0], lane & 0x1C);
    float l1 = __shfl_sync(0xffffffffu, acc[32][2], lane & 0x1C);
    const float g = gamma_p[0];
    const float gl0 = g / l0;
    const float gl1 = g / l1;

    const int jA = j0 + w * 16 + (lane >> 2);
    const int cb = (lane & 3) * 2;
#pragma unroll
    for (int nc = 0; nc < 32; nc++) {
        int c = nc * 8 + cb;
        size_t o00 = ((size_t)(b * GC + c)) * GN + jA;   // (c,   jA)
        size_t o10 = o00 + GN;                            // (c+1, jA)
        out[o00]     = gl0 * acc[nc][0] + x[o00];
        out[o10]     = gl0 * acc[nc][1] + x[o10];
        out[o00 + 8] = gl1 * acc[nc][2] + x[o00 + 8];    // (c,   jA+8)
        out[o10 + 8] = gl1 * acc[nc][3] + x[o10 + 8];    // (c+1, jA+8)
    }
}

extern "C" void kernel_launch(void* const* d_in, const int* in_sizes, int n_in,
                              void* d_out, int out_size) {
    const float* x     = (const float*)d_in[0];
    const float* w     = (const float*)d_in[1];
    const float* gamma = (const float*)d_in[2];
    float* out = (float*)d_out;

    cudaFuncSetAttribute(attn_kernel,
                         cudaFuncAttributeMaxDynamicSharedMemorySize, SMEM_TOTAL);

    dim3 g1(GN / 64, GO / 64, 2);      // (144, 5, 2)
    qkv_gemm<<<g1, 256>>>(x, w);

    dim3 g2(NT, 2);                    // (72, 2) = 144 CTAs ~ 1 wave
    attn_kernel<<<g2, 256, SMEM_TOTAL>>>(x, gamma, out);
}